// round 1
// baseline (speedup 1.0000x reference)
#include <cuda_runtime.h>

#define Pl (128*128)
#define V  (128*128*128)

typedef unsigned long long u64;

__device__ __forceinline__ u64 pk(float lo, float hi) {
    u64 r; asm("mov.b64 %0,{%1,%2};" : "=l"(r) : "f"(lo), "f"(hi)); return r;
}
__device__ __forceinline__ void fma2(u64 &d, u64 a, u64 b) {
    asm("fma.rn.f32x2 %0,%1,%2,%0;" : "+l"(d) : "l"(a), "l"(b));
}
__device__ __forceinline__ float2 upk(u64 a) {
    float2 f; asm("mov.b64 {%0,%1},%2;" : "=f"(f.x), "=f"(f.y) : "l"(a)); return f;
}

// Scratch (no allocations allowed): h [8,128^3], w-field [27,128^3], ping-pong [8,128^3]
__device__ float g_h[8 * V];
__device__ float g_w[27 * V];
__device__ float g_t[8 * V];

// ---------------------------------------------------------------------------
// conv1: x[8,D,H,W] -> g_h = relu(conv3x3x3(x, w1) + b1), 8->8 channels
// block (16,8): thread = 8 consecutive x positions, all 8 out channels
// ---------------------------------------------------------------------------
__global__ __launch_bounds__(128) void k_conv1(const float* __restrict__ x,
                                               const float* __restrict__ w1,
                                               const float* __restrict__ b1)
{
    __shared__ float2 ws[8 * 27 * 8];   // [ic][tap][oc] duplicated pairs
    __shared__ float2 bs[8];
    int tid = threadIdx.y * 16 + threadIdx.x;
    for (int i = tid; i < 1728; i += 128) {
        int oc = i / 216, rem = i % 216, ic = rem / 27, t = rem % 27;
        float v = w1[i];                 // w1 layout [oc][ic][t]
        ws[(ic * 27 + t) * 8 + oc] = make_float2(v, v);
    }
    if (tid < 8) bs[tid] = make_float2(b1[tid], b1[tid]);
    __syncthreads();

    int x0 = threadIdx.x * 8;
    int y  = blockIdx.x * 8 + threadIdx.y;
    int z  = blockIdx.y;

    u64 acc[8][4];
    #pragma unroll
    for (int oc = 0; oc < 8; oc++) {
        u64 b = *reinterpret_cast<const u64*>(&bs[oc]);
        acc[oc][0] = b; acc[oc][1] = b; acc[oc][2] = b; acc[oc][3] = b;
    }

    for (int ic = 0; ic < 8; ic++) {
        const float* xc = x + (size_t)ic * V;
        for (int dz = 0; dz < 3; dz++) {
            int zz = z + dz - 1; if ((unsigned)zz >= 128u) continue;
            for (int dy = 0; dy < 3; dy++) {
                int yy = y + dy - 1; if ((unsigned)yy >= 128u) continue;
                const float* r = xc + (size_t)zz * Pl + yy * 128 + x0;
                float in0 = (x0 > 0) ? r[-1] : 0.f;
                float4 a4 = *reinterpret_cast<const float4*>(r);
                float4 b4 = *reinterpret_cast<const float4*>(r + 4);
                float in9 = (x0 < 120) ? r[8] : 0.f;
                float in[10] = {in0, a4.x, a4.y, a4.z, a4.w, b4.x, b4.y, b4.z, b4.w, in9};
                u64 p[9];
                #pragma unroll
                for (int k = 0; k < 9; k++) p[k] = pk(in[k], in[k + 1]);
                const u64* wq = reinterpret_cast<const u64*>(&ws[(ic * 27 + (dz * 3 + dy) * 3) * 8]);
                #pragma unroll
                for (int s = 0; s < 3; s++) {
                    #pragma unroll
                    for (int oc = 0; oc < 8; oc++) {
                        u64 w = wq[s * 8 + oc];
                        fma2(acc[oc][0], p[s + 0], w);
                        fma2(acc[oc][1], p[s + 2], w);
                        fma2(acc[oc][2], p[s + 4], w);
                        fma2(acc[oc][3], p[s + 6], w);
                    }
                }
            }
        }
    }
    size_t ob = (size_t)z * Pl + y * 128 + x0;
    #pragma unroll
    for (int oc = 0; oc < 8; oc++) {
        float2 v0 = upk(acc[oc][0]), v1 = upk(acc[oc][1]);
        float2 v2 = upk(acc[oc][2]), v3 = upk(acc[oc][3]);
        float4 f0 = make_float4(fmaxf(v0.x, 0.f), fmaxf(v0.y, 0.f), fmaxf(v1.x, 0.f), fmaxf(v1.y, 0.f));
        float4 f1 = make_float4(fmaxf(v2.x, 0.f), fmaxf(v2.y, 0.f), fmaxf(v3.x, 0.f), fmaxf(v3.y, 0.f));
        *reinterpret_cast<float4*>(&g_h[(size_t)oc * V + ob])     = f0;
        *reinterpret_cast<float4*>(&g_h[(size_t)oc * V + ob + 4]) = f1;
    }
}

// ---------------------------------------------------------------------------
// conv2: g_h -> g_w = conv3x3x3(h, w2), 8->27 channels (grid.z = oc group of 9)
// ---------------------------------------------------------------------------
__global__ __launch_bounds__(128) void k_conv2(const float* __restrict__ w2)
{
    __shared__ float2 ws[8 * 27 * 9];   // [ic][tap][o9]
    int tid = threadIdx.y * 16 + threadIdx.x;
    int grp = blockIdx.z;
    for (int i = tid; i < 8 * 27 * 9; i += 128) {
        int o9 = i % 9; int it = i / 9; int t = it % 27; int ic = it / 27;
        int oc = grp * 9 + o9;
        float v = w2[(oc * 8 + ic) * 27 + t];   // w2 layout [27][8][t]
        ws[i] = make_float2(v, v);
    }
    __syncthreads();

    int x0 = threadIdx.x * 8;
    int y  = blockIdx.x * 8 + threadIdx.y;
    int z  = blockIdx.y;

    u64 acc[9][4];
    #pragma unroll
    for (int o = 0; o < 9; o++) { acc[o][0] = 0; acc[o][1] = 0; acc[o][2] = 0; acc[o][3] = 0; }

    for (int ic = 0; ic < 8; ic++) {
        const float* xc = g_h + (size_t)ic * V;
        for (int dz = 0; dz < 3; dz++) {
            int zz = z + dz - 1; if ((unsigned)zz >= 128u) continue;
            for (int dy = 0; dy < 3; dy++) {
                int yy = y + dy - 1; if ((unsigned)yy >= 128u) continue;
                const float* r = xc + (size_t)zz * Pl + yy * 128 + x0;
                float in0 = (x0 > 0) ? r[-1] : 0.f;
                float4 a4 = *reinterpret_cast<const float4*>(r);
                float4 b4 = *reinterpret_cast<const float4*>(r + 4);
                float in9 = (x0 < 120) ? r[8] : 0.f;
                float in[10] = {in0, a4.x, a4.y, a4.z, a4.w, b4.x, b4.y, b4.z, b4.w, in9};
                u64 p[9];
                #pragma unroll
                for (int k = 0; k < 9; k++) p[k] = pk(in[k], in[k + 1]);
                #pragma unroll
                for (int s = 0; s < 3; s++) {
                    const u64* wq = reinterpret_cast<const u64*>(&ws[(ic * 27 + (dz * 3 + dy) * 3 + s) * 9]);
                    #pragma unroll
                    for (int o = 0; o < 9; o++) {
                        u64 w = wq[o];
                        fma2(acc[o][0], p[s + 0], w);
                        fma2(acc[o][1], p[s + 2], w);
                        fma2(acc[o][2], p[s + 4], w);
                        fma2(acc[o][3], p[s + 6], w);
                    }
                }
            }
        }
    }
    size_t ob = (size_t)z * Pl + y * 128 + x0;
    #pragma unroll
    for (int o = 0; o < 9; o++) {
        float2 v0 = upk(acc[o][0]), v1 = upk(acc[o][1]);
        float2 v2 = upk(acc[o][2]), v3 = upk(acc[o][3]);
        float4 f0 = make_float4(v0.x, v0.y, v1.x, v1.y);
        float4 f1 = make_float4(v2.x, v2.y, v3.x, v3.y);
        size_t base = (size_t)(grp * 9 + o) * V + ob;
        *reinterpret_cast<float4*>(&g_w[base])     = f0;
        *reinterpret_cast<float4*>(&g_w[base + 4]) = f1;
    }
}

// ---------------------------------------------------------------------------
// normalize: per-voxel L1-normalize g_w over the 27 channels (in place)
// ---------------------------------------------------------------------------
__global__ __launch_bounds__(256) void k_norm()
{
    size_t i = ((size_t)blockIdx.x * 256 + threadIdx.x) * 2;
    float2 v[27];
    float sx = 0.f, sy = 0.f;
    #pragma unroll
    for (int t = 0; t < 27; t++) {
        v[t] = *reinterpret_cast<const float2*>(&g_w[(size_t)t * V + i]);
        sx += fabsf(v[t].x);
        sy += fabsf(v[t].y);
    }
    float rx = 1.f / fmaxf(sx, 1e-12f);
    float ry = 1.f / fmaxf(sy, 1e-12f);
    #pragma unroll
    for (int t = 0; t < 27; t++) {
        v[t].x *= rx; v[t].y *= ry;
        *reinterpret_cast<float2*>(&g_w[(size_t)t * V + i]) = v[t];
    }
}

// ---------------------------------------------------------------------------
// adaptive conv: out_c(p) = sum_t w_t(p) * in_c(p + off_t), 8 channels
// src: 0=x, 1=g_t, 2=g_h ; dst: 0=dout, 1=g_t, 2=g_h
// ---------------------------------------------------------------------------
__global__ __launch_bounds__(128) void k_adapt(const float* xin, float* dout,
                                               int src, int dst)
{
    const float* in  = (src == 0) ? xin : (src == 1 ? g_t : g_h);
    float*       out = (dst == 1) ? g_t : (dst == 2 ? g_h : dout);

    int x0 = threadIdx.x * 8;
    int y  = blockIdx.x * 8 + threadIdx.y;
    int z  = blockIdx.y;
    size_t ob = (size_t)z * Pl + y * 128 + x0;

    for (int chunk = 0; chunk < 2; chunk++) {
        u64 acc[4][4];
        #pragma unroll
        for (int c = 0; c < 4; c++) { acc[c][0] = 0; acc[c][1] = 0; acc[c][2] = 0; acc[c][3] = 0; }

        for (int dz = 0; dz < 3; dz++) {
            int zz = z + dz - 1; if ((unsigned)zz >= 128u) continue;
            for (int dy = 0; dy < 3; dy++) {
                int yy = y + dy - 1; if ((unsigned)yy >= 128u) continue;
                // per-voxel weights at the OUTPUT position (aligned pairs)
                u64 q[3][4];
                #pragma unroll
                for (int s = 0; s < 3; s++) {
                    const float* wr = g_w + (size_t)(dz * 9 + dy * 3 + s) * V + ob;
                    float4 w0 = *reinterpret_cast<const float4*>(wr);
                    float4 w1 = *reinterpret_cast<const float4*>(wr + 4);
                    q[s][0] = pk(w0.x, w0.y); q[s][1] = pk(w0.z, w0.w);
                    q[s][2] = pk(w1.x, w1.y); q[s][3] = pk(w1.z, w1.w);
                }
                #pragma unroll
                for (int c = 0; c < 4; c++) {
                    const float* r = in + (size_t)(chunk * 4 + c) * V + (size_t)zz * Pl + yy * 128 + x0;
                    float in0 = (x0 > 0) ? r[-1] : 0.f;
                    float4 a4 = *reinterpret_cast<const float4*>(r);
                    float4 b4 = *reinterpret_cast<const float4*>(r + 4);
                    float in9 = (x0 < 120) ? r[8] : 0.f;
                    float iv[10] = {in0, a4.x, a4.y, a4.z, a4.w, b4.x, b4.y, b4.z, b4.w, in9};
                    u64 p[9];
                    #pragma unroll
                    for (int k = 0; k < 9; k++) p[k] = pk(iv[k], iv[k + 1]);
                    #pragma unroll
                    for (int s = 0; s < 3; s++) {
                        fma2(acc[c][0], p[s + 0], q[s][0]);
                        fma2(acc[c][1], p[s + 2], q[s][1]);
                        fma2(acc[c][2], p[s + 4], q[s][2]);
                        fma2(acc[c][3], p[s + 6], q[s][3]);
                    }
                }
            }
        }
        #pragma unroll
        for (int c = 0; c < 4; c++) {
            float2 v0 = upk(acc[c][0]), v1 = upk(acc[c][1]);
            float2 v2 = upk(acc[c][2]), v3 = upk(acc[c][3]);
            float4 f0 = make_float4(v0.x, v0.y, v1.x, v1.y);
            float4 f1 = make_float4(v2.x, v2.y, v3.x, v3.y);
            size_t base = (size_t)(chunk * 4 + c) * V + ob;
            *reinterpret_cast<float4*>(&out[base])     = f0;
            *reinterpret_cast<float4*>(&out[base + 4]) = f1;
        }
    }
}

// ---------------------------------------------------------------------------
extern "C" void kernel_launch(void* const* d_in, const int* in_sizes, int n_in,
                              void* d_out, int out_size)
{
    // default positional, override by unique element counts for safety
    const float* x  = (const float*)d_in[0];
    const float* w1 = (n_in > 1) ? (const float*)d_in[1] : nullptr;
    const float* b1 = (n_in > 2) ? (const float*)d_in[2] : nullptr;
    const float* w2 = (n_in > 3) ? (const float*)d_in[3] : nullptr;
    for (int i = 0; i < n_in; i++) {
        switch (in_sizes[i]) {
            case 8 * V: x  = (const float*)d_in[i]; break;   // 16777216
            case 1728:  w1 = (const float*)d_in[i]; break;
            case 8:     b1 = (const float*)d_in[i]; break;
            case 5832:  w2 = (const float*)d_in[i]; break;
            default: break;
        }
    }

    dim3 blk(16, 8);
    dim3 g1(16, 128);

    k_conv1<<<g1, blk>>>(x, w1, b1);
    k_conv2<<<dim3(16, 128, 3), blk>>>(w2);
    k_norm<<<4096, 256>>>();

    float* out = (float*)d_out;
    k_adapt<<<g1, blk>>>(x, out, 0, 1);   // x    -> g_t
    k_adapt<<<g1, blk>>>(x, out, 1, 2);   // g_t  -> g_h
    k_adapt<<<g1, blk>>>(x, out, 2, 0);   // g_h  -> d_out
}

// round 4
// speedup vs baseline: 1.0272x; 1.0272x over previous
#include <cuda_runtime.h>

#define Pl (128*128)
#define V  (128*128*128)

typedef unsigned long long u64;

__device__ __forceinline__ u64 pk(float lo, float hi) {
    u64 r; asm("mov.b64 %0,{%1,%2};" : "=l"(r) : "f"(lo), "f"(hi)); return r;
}
__device__ __forceinline__ void fma2(u64 &d, u64 a, u64 b) {
    asm("fma.rn.f32x2 %0,%1,%2,%0;" : "+l"(d) : "l"(a), "l"(b));
}
__device__ __forceinline__ u64 mul2(u64 a, u64 b) {
    u64 r; asm("mul.rn.f32x2 %0,%1,%2;" : "=l"(r) : "l"(a), "l"(b)); return r;
}
__device__ __forceinline__ u64 add2(u64 a, u64 b) {
    u64 r; asm("add.rn.f32x2 %0,%1,%2;" : "=l"(r) : "l"(a), "l"(b)); return r;
}
__device__ __forceinline__ u64 abs2(u64 a) { return a & 0x7FFFFFFF7FFFFFFFULL; }
__device__ __forceinline__ float2 upk(u64 a) {
    float2 f; asm("mov.b64 {%0,%1},%2;" : "=f"(f.x), "=f"(f.y) : "l"(a)); return f;
}

// Scratch (no allocations allowed)
__device__ float g_h[8 * V];
__device__ float g_w[27 * V];   // UNNORMALIZED conv2 output; normalization fused into adapt
__device__ float g_t[8 * V];

// ---------------------------------------------------------------------------
// conv1: x[8,D,H,W] -> g_h = relu(conv3x3x3(x, w1) + b1), 8->8 channels
// ---------------------------------------------------------------------------
__global__ __launch_bounds__(128) void k_conv1(const float* __restrict__ x,
                                               const float* __restrict__ w1,
                                               const float* __restrict__ b1)
{
    __shared__ float2 ws[8 * 27 * 8];   // [ic][tap][oc] duplicated pairs
    __shared__ float2 bs[8];
    int tid = threadIdx.y * 16 + threadIdx.x;
    for (int i = tid; i < 1728; i += 128) {
        int oc = i / 216, rem = i % 216, ic = rem / 27, t = rem % 27;
        float v = w1[i];                 // w1 layout [oc][ic][t]
        ws[(ic * 27 + t) * 8 + oc] = make_float2(v, v);
    }
    if (tid < 8) bs[tid] = make_float2(b1[tid], b1[tid]);
    __syncthreads();

    int x0 = threadIdx.x * 8;
    int y  = blockIdx.x * 8 + threadIdx.y;
    int z  = blockIdx.y;

    u64 acc[8][4];
    #pragma unroll
    for (int oc = 0; oc < 8; oc++) {
        u64 b = *reinterpret_cast<const u64*>(&bs[oc]);
        acc[oc][0] = b; acc[oc][1] = b; acc[oc][2] = b; acc[oc][3] = b;
    }

    for (int ic = 0; ic < 8; ic++) {
        const float* xc = x + (size_t)ic * V;
        for (int dz = 0; dz < 3; dz++) {
            int zz = z + dz - 1; if ((unsigned)zz >= 128u) continue;
            for (int dy = 0; dy < 3; dy++) {
                int yy = y + dy - 1; if ((unsigned)yy >= 128u) continue;
                const float* r = xc + (size_t)zz * Pl + yy * 128 + x0;
                float in0 = (x0 > 0) ? r[-1] : 0.f;
                float4 a4 = *reinterpret_cast<const float4*>(r);
                float4 b4 = *reinterpret_cast<const float4*>(r + 4);
                float in9 = (x0 < 120) ? r[8] : 0.f;
                float in[10] = {in0, a4.x, a4.y, a4.z, a4.w, b4.x, b4.y, b4.z, b4.w, in9};
                u64 p[9];
                #pragma unroll
                for (int k = 0; k < 9; k++) p[k] = pk(in[k], in[k + 1]);
                const u64* wq = reinterpret_cast<const u64*>(&ws[(ic * 27 + (dz * 3 + dy) * 3) * 8]);
                #pragma unroll
                for (int s = 0; s < 3; s++) {
                    #pragma unroll
                    for (int oc = 0; oc < 8; oc++) {
                        u64 w = wq[s * 8 + oc];
                        fma2(acc[oc][0], p[s + 0], w);
                        fma2(acc[oc][1], p[s + 2], w);
                        fma2(acc[oc][2], p[s + 4], w);
                        fma2(acc[oc][3], p[s + 6], w);
                    }
                }
            }
        }
    }
    size_t ob = (size_t)z * Pl + y * 128 + x0;
    #pragma unroll
    for (int oc = 0; oc < 8; oc++) {
        float2 v0 = upk(acc[oc][0]), v1 = upk(acc[oc][1]);
        float2 v2 = upk(acc[oc][2]), v3 = upk(acc[oc][3]);
        float4 f0 = make_float4(fmaxf(v0.x, 0.f), fmaxf(v0.y, 0.f), fmaxf(v1.x, 0.f), fmaxf(v1.y, 0.f));
        float4 f1 = make_float4(fmaxf(v2.x, 0.f), fmaxf(v2.y, 0.f), fmaxf(v3.x, 0.f), fmaxf(v3.y, 0.f));
        *reinterpret_cast<float4*>(&g_h[(size_t)oc * V + ob])     = f0;
        *reinterpret_cast<float4*>(&g_h[(size_t)oc * V + ob + 4]) = f1;
    }
}

// ---------------------------------------------------------------------------
// conv2: g_h -> g_w = conv3x3x3(h, w2), 8->27 channels (grid.z = oc group of 9)
// ---------------------------------------------------------------------------
__global__ __launch_bounds__(128) void k_conv2(const float* __restrict__ w2)
{
    __shared__ float2 ws[8 * 27 * 9];   // [ic][tap][o9]
    int tid = threadIdx.y * 16 + threadIdx.x;
    int grp = blockIdx.z;
    for (int i = tid; i < 8 * 27 * 9; i += 128) {
        int o9 = i % 9; int it = i / 9; int t = it % 27; int ic = it / 27;
        int oc = grp * 9 + o9;
        float v = w2[(oc * 8 + ic) * 27 + t];   // w2 layout [27][8][t]
        ws[i] = make_float2(v, v);
    }
    __syncthreads();

    int x0 = threadIdx.x * 8;
    int y  = blockIdx.x * 8 + threadIdx.y;
    int z  = blockIdx.y;

    u64 acc[9][4];
    #pragma unroll
    for (int o = 0; o < 9; o++) { acc[o][0] = 0; acc[o][1] = 0; acc[o][2] = 0; acc[o][3] = 0; }

    for (int ic = 0; ic < 8; ic++) {
        const float* xc = g_h + (size_t)ic * V;
        for (int dz = 0; dz < 3; dz++) {
            int zz = z + dz - 1; if ((unsigned)zz >= 128u) continue;
            for (int dy = 0; dy < 3; dy++) {
                int yy = y + dy - 1; if ((unsigned)yy >= 128u) continue;
                const float* r = xc + (size_t)zz * Pl + yy * 128 + x0;
                float in0 = (x0 > 0) ? r[-1] : 0.f;
                float4 a4 = *reinterpret_cast<const float4*>(r);
                float4 b4 = *reinterpret_cast<const float4*>(r + 4);
                float in9 = (x0 < 120) ? r[8] : 0.f;
                float in[10] = {in0, a4.x, a4.y, a4.z, a4.w, b4.x, b4.y, b4.z, b4.w, in9};
                u64 p[9];
                #pragma unroll
                for (int k = 0; k < 9; k++) p[k] = pk(in[k], in[k + 1]);
                #pragma unroll
                for (int s = 0; s < 3; s++) {
                    const u64* wq = reinterpret_cast<const u64*>(&ws[(ic * 27 + (dz * 3 + dy) * 3 + s) * 9]);
                    #pragma unroll
                    for (int o = 0; o < 9; o++) {
                        u64 w = wq[o];
                        fma2(acc[o][0], p[s + 0], w);
                        fma2(acc[o][1], p[s + 2], w);
                        fma2(acc[o][2], p[s + 4], w);
                        fma2(acc[o][3], p[s + 6], w);
                    }
                }
            }
        }
    }
    size_t ob = (size_t)z * Pl + y * 128 + x0;
    #pragma unroll
    for (int o = 0; o < 9; o++) {
        float2 v0 = upk(acc[o][0]), v1 = upk(acc[o][1]);
        float2 v2 = upk(acc[o][2]), v3 = upk(acc[o][3]);
        float4 f0 = make_float4(v0.x, v0.y, v1.x, v1.y);
        float4 f1 = make_float4(v2.x, v2.y, v3.x, v3.y);
        size_t base = (size_t)(grp * 9 + o) * V + ob;
        *reinterpret_cast<float4*>(&g_w[base])     = f0;
        *reinterpret_cast<float4*>(&g_w[base + 4]) = f1;
    }
}

// ---------------------------------------------------------------------------
// adaptive conv with FUSED L1 normalization:
//   n(p)   = sum_t |w_t(p)|            (all 27 taps, independent of bounds)
//   out_c(p) = (1/max(n,1e-12)) * sum_t w_t(p) * in_c(p + off_t)
// All 8 channels per thread -> weight field read exactly once per pass.
// src: 0=x, 1=g_t, 2=g_h ; dst: 0=dout, 1=g_t, 2=g_h
// ---------------------------------------------------------------------------
__global__ __launch_bounds__(128) void k_adapt(const float* __restrict__ xin,
                                               float* __restrict__ dout,
                                               int src, int dst)
{
    const float* in  = (src == 0) ? xin : (src == 1 ? g_t : g_h);
    float*       out = (dst == 1) ? g_t : (dst == 2 ? g_h : dout);

    int x0 = threadIdx.x * 8;
    int y  = blockIdx.x * 8 + threadIdx.y;
    int z  = blockIdx.y;
    size_t ob = (size_t)z * Pl + y * 128 + x0;

    u64 acc[8][4];
    #pragma unroll
    for (int c = 0; c < 8; c++) { acc[c][0] = 0; acc[c][1] = 0; acc[c][2] = 0; acc[c][3] = 0; }
    u64 nrm[4] = {0, 0, 0, 0};

    #pragma unroll
    for (int dz = 0; dz < 3; dz++) {
        int zz = z + dz - 1;
        bool zin = (unsigned)zz < 128u;
        #pragma unroll
        for (int dy = 0; dy < 3; dy++) {
            int yy = y + dy - 1;
            bool yin = (unsigned)yy < 128u;

            // per-voxel weights at the OUTPUT position -- always loaded
            // (the L1 norm includes every tap regardless of neighbor validity)
            u64 q[3][4];
            #pragma unroll
            for (int s = 0; s < 3; s++) {
                const float* wr = g_w + (size_t)(dz * 9 + dy * 3 + s) * V + ob;
                float4 w0 = *reinterpret_cast<const float4*>(wr);
                float4 w1 = *reinterpret_cast<const float4*>(wr + 4);
                q[s][0] = pk(w0.x, w0.y); q[s][1] = pk(w0.z, w0.w);
                q[s][2] = pk(w1.x, w1.y); q[s][3] = pk(w1.z, w1.w);
                #pragma unroll
                for (int j = 0; j < 4; j++) nrm[j] = add2(nrm[j], abs2(q[s][j]));
            }

            if (zin && yin) {
                #pragma unroll
                for (int c = 0; c < 8; c++) {
                    const float* r = in + (size_t)c * V + (size_t)zz * Pl + yy * 128 + x0;
                    float in0 = (x0 > 0) ? r[-1] : 0.f;
                    float4 a4 = *reinterpret_cast<const float4*>(r);
                    float4 b4 = *reinterpret_cast<const float4*>(r + 4);
                    float in9 = (x0 < 120) ? r[8] : 0.f;
                    float iv[10] = {in0, a4.x, a4.y, a4.z, a4.w, b4.x, b4.y, b4.z, b4.w, in9};
                    u64 p[9];
                    #pragma unroll
                    for (int k = 0; k < 9; k++) p[k] = pk(iv[k], iv[k + 1]);
                    #pragma unroll
                    for (int s = 0; s < 3; s++) {
                        fma2(acc[c][0], p[s + 0], q[s][0]);
                        fma2(acc[c][1], p[s + 2], q[s][1]);
                        fma2(acc[c][2], p[s + 4], q[s][2]);
                        fma2(acc[c][3], p[s + 6], q[s][3]);
                    }
                }
            }
        }
    }

    // reciprocal of per-voxel L1 norm (packed)
    u64 rn[4];
    #pragma unroll
    for (int j = 0; j < 4; j++) {
        float2 n2 = upk(nrm[j]);
        float rx = 1.f / fmaxf(n2.x, 1e-12f);
        float ry = 1.f / fmaxf(n2.y, 1e-12f);
        rn[j] = pk(rx, ry);
    }

    #pragma unroll
    for (int c = 0; c < 8; c++) {
        float2 v0 = upk(mul2(acc[c][0], rn[0]));
        float2 v1 = upk(mul2(acc[c][1], rn[1]));
        float2 v2 = upk(mul2(acc[c][2], rn[2]));
        float2 v3 = upk(mul2(acc[c][3], rn[3]));
        float4 f0 = make_float4(v0.x, v0.y, v1.x, v1.y);
        float4 f1 = make_float4(v2.x, v2.y, v3.x, v3.y);
        size_t base = (size_t)c * V + ob;
        *reinterpret_cast<float4*>(&out[base])     = f0;
        *reinterpret_cast<float4*>(&out[base + 4]) = f1;
    }
}

// ---------------------------------------------------------------------------
extern "C" void kernel_launch(void* const* d_in, const int* in_sizes, int n_in,
                              void* d_out, int out_size)
{
    const float* x  = (const float*)d_in[0];
    const float* w1 = (n_in > 1) ? (const float*)d_in[1] : nullptr;
    const float* b1 = (n_in > 2) ? (const float*)d_in[2] : nullptr;
    const float* w2 = (n_in > 3) ? (const float*)d_in[3] : nullptr;
    for (int i = 0; i < n_in; i++) {
        switch (in_sizes[i]) {
            case 8 * V: x  = (const float*)d_in[i]; break;
            case 1728:  w1 = (const float*)d_in[i]; break;
            case 8:     b1 = (const float*)d_in[i]; break;
            case 5832:  w2 = (const float*)d_in[i]; break;
            default: break;
        }
    }

    dim3 blk(16, 8);
    dim3 g1(16, 128);

    k_conv1<<<g1, blk>>>(x, w1, b1);
    k_conv2<<<dim3(16, 128, 3), blk>>>(w2);

    float* out = (float*)d_out;
    k_adapt<<<g1, blk>>>(x, out, 0, 1);   // x    -> g_t   (fused normalize)
    k_adapt<<<g1, blk>>>(x, out, 1, 2);   // g_t  -> g_h
    k_adapt<<<g1, blk>>>(x, out, 2, 0);   // g_h  -> d_out
}

// round 5
// speedup vs baseline: 1.1542x; 1.1237x over previous
#include <cuda_runtime.h>

#define Pl  (128*128)
#define V   (128*128*128)
#define PX  136
#define PPl (130*136)
#define PV  (130*130*136)

typedef unsigned long long u64;

__device__ __forceinline__ u64 pk(float lo, float hi) {
    u64 r; asm("mov.b64 %0,{%1,%2};" : "=l"(r) : "f"(lo), "f"(hi)); return r;
}
__device__ __forceinline__ void fma2(u64 &d, u64 a, u64 b) {
    asm("fma.rn.f32x2 %0,%1,%2,%0;" : "+l"(d) : "l"(a), "l"(b));
}
__device__ __forceinline__ u64 mul2(u64 a, u64 b) {
    u64 r; asm("mul.rn.f32x2 %0,%1,%2;" : "=l"(r) : "l"(a), "l"(b)); return r;
}
__device__ __forceinline__ u64 add2(u64 a, u64 b) {
    u64 r; asm("add.rn.f32x2 %0,%1,%2;" : "=l"(r) : "l"(a), "l"(b)); return r;
}
__device__ __forceinline__ u64 abs2(u64 a) { return a & 0x7FFFFFFF7FFFFFFFULL; }
__device__ __forceinline__ float2 upk(u64 a) {
    float2 f; asm("mov.b64 {%0,%1},%2;" : "=f"(f.x), "=f"(f.y) : "l"(a)); return f;
}

// Padded scratch: [8][130][130][136], data voxel (z,y,x) at (z+1, y+1, x+4).
__device__ float g_xp[8 * PV];
__device__ float g_hp[8 * PV];
__device__ float g_tp[8 * PV];
__device__ float g_w [27 * V];   // unnormalized conv2 output (flat)

// ---------------------------------------------------------------------------
// pad: build g_xp (zero halo + copy x); zero halos of g_hp and g_tp
// ---------------------------------------------------------------------------
__global__ __launch_bounds__(160) void k_pad(const float* __restrict__ x)
{
    int row = blockIdx.x;                 // 8*130*130 rows
    int xx  = threadIdx.x;
    if (xx >= PX) return;
    int c   = row / (130 * 130);
    int rem = row % (130 * 130);
    int zz  = rem / 130;
    int yy  = rem % 130;
    bool halo = (zz == 0) | (zz == 129) | (yy == 0) | (yy == 129) | (xx < 4) | (xx >= 132);
    size_t po = (size_t)c * PV + zz * PPl + yy * PX + xx;
    float v = 0.f;
    if (!halo)
        v = x[(size_t)c * V + (size_t)(zz - 1) * Pl + (yy - 1) * 128 + (xx - 4)];
    g_xp[po] = v;
    if (halo) { g_hp[po] = 0.f; g_tp[po] = 0.f; }
}

// ---------------------------------------------------------------------------
// conv1: g_xp -> g_hp = relu(conv3x3x3(x, w1) + b1), 8->8 channels
// block (16,8): thread = 8 consecutive x, all 8 oc. Fully unrolled taps.
// ---------------------------------------------------------------------------
__global__ __launch_bounds__(128) void k_conv1(const float* __restrict__ w1,
                                               const float* __restrict__ b1)
{
    __shared__ float2 ws[8 * 27 * 8];   // [ic][tap][oc] duplicated pairs
    __shared__ float2 bs[8];
    int tid = threadIdx.y * 16 + threadIdx.x;
    for (int i = tid; i < 1728; i += 128) {
        int oc = i / 216, rem = i % 216, ic = rem / 27, t = rem % 27;
        float v = w1[i];                 // w1 layout [oc][ic][t]
        ws[(ic * 27 + t) * 8 + oc] = make_float2(v, v);
    }
    if (tid < 8) bs[tid] = make_float2(b1[tid], b1[tid]);
    __syncthreads();

    int x0 = threadIdx.x * 8;
    int y  = blockIdx.x * 8 + threadIdx.y;
    int z  = blockIdx.y;

    u64 acc[8][4];
    #pragma unroll
    for (int oc = 0; oc < 8; oc++) {
        u64 b = *reinterpret_cast<const u64*>(&bs[oc]);
        acc[oc][0] = b; acc[oc][1] = b; acc[oc][2] = b; acc[oc][3] = b;
    }

    #pragma unroll 1
    for (int ic = 0; ic < 8; ic++) {
        const float* xc = g_xp + (size_t)ic * PV + (size_t)z * PPl + y * PX + x0 + 3;
        #pragma unroll
        for (int dz = 0; dz < 3; dz++) {
            #pragma unroll
            for (int dy = 0; dy < 3; dy++) {
                const float* r = xc + dz * PPl + dy * PX;
                float in0 = r[0];
                float4 a4 = *reinterpret_cast<const float4*>(r + 1);
                float4 b4 = *reinterpret_cast<const float4*>(r + 5);
                float in9 = r[9];
                float in[10] = {in0, a4.x, a4.y, a4.z, a4.w, b4.x, b4.y, b4.z, b4.w, in9};
                u64 p[9];
                #pragma unroll
                for (int k = 0; k < 9; k++) p[k] = pk(in[k], in[k + 1]);
                const u64* wq = reinterpret_cast<const u64*>(&ws[(ic * 27 + (dz * 3 + dy) * 3) * 8]);
                #pragma unroll
                for (int s = 0; s < 3; s++) {
                    #pragma unroll
                    for (int oc = 0; oc < 8; oc++) {
                        u64 w = wq[s * 8 + oc];
                        fma2(acc[oc][0], p[s + 0], w);
                        fma2(acc[oc][1], p[s + 2], w);
                        fma2(acc[oc][2], p[s + 4], w);
                        fma2(acc[oc][3], p[s + 6], w);
                    }
                }
            }
        }
    }
    size_t ob = (size_t)(z + 1) * PPl + (y + 1) * PX + (x0 + 4);
    #pragma unroll
    for (int oc = 0; oc < 8; oc++) {
        float2 v0 = upk(acc[oc][0]), v1 = upk(acc[oc][1]);
        float2 v2 = upk(acc[oc][2]), v3 = upk(acc[oc][3]);
        float4 f0 = make_float4(fmaxf(v0.x, 0.f), fmaxf(v0.y, 0.f), fmaxf(v1.x, 0.f), fmaxf(v1.y, 0.f));
        float4 f1 = make_float4(fmaxf(v2.x, 0.f), fmaxf(v2.y, 0.f), fmaxf(v3.x, 0.f), fmaxf(v3.y, 0.f));
        *reinterpret_cast<float4*>(&g_hp[(size_t)oc * PV + ob])     = f0;
        *reinterpret_cast<float4*>(&g_hp[(size_t)oc * PV + ob + 4]) = f1;
    }
}

// ---------------------------------------------------------------------------
// conv2: g_hp -> g_w = conv3x3x3(h, w2), 8->27 channels (grid.z = group of 9)
// ---------------------------------------------------------------------------
__global__ __launch_bounds__(128) void k_conv2(const float* __restrict__ w2)
{
    __shared__ float2 ws[8 * 27 * 9];   // [ic][tap][o9]
    int tid = threadIdx.y * 16 + threadIdx.x;
    int grp = blockIdx.z;
    for (int i = tid; i < 8 * 27 * 9; i += 128) {
        int o9 = i % 9; int it = i / 9; int t = it % 27; int ic = it / 27;
        int oc = grp * 9 + o9;
        float v = w2[(oc * 8 + ic) * 27 + t];   // w2 layout [27][8][t]
        ws[i] = make_float2(v, v);
    }
    __syncthreads();

    int x0 = threadIdx.x * 8;
    int y  = blockIdx.x * 8 + threadIdx.y;
    int z  = blockIdx.y;

    u64 acc[9][4];
    #pragma unroll
    for (int o = 0; o < 9; o++) { acc[o][0] = 0; acc[o][1] = 0; acc[o][2] = 0; acc[o][3] = 0; }

    #pragma unroll 1
    for (int ic = 0; ic < 8; ic++) {
        const float* xc = g_hp + (size_t)ic * PV + (size_t)z * PPl + y * PX + x0 + 3;
        #pragma unroll
        for (int dz = 0; dz < 3; dz++) {
            #pragma unroll
            for (int dy = 0; dy < 3; dy++) {
                const float* r = xc + dz * PPl + dy * PX;
                float in0 = r[0];
                float4 a4 = *reinterpret_cast<const float4*>(r + 1);
                float4 b4 = *reinterpret_cast<const float4*>(r + 5);
                float in9 = r[9];
                float in[10] = {in0, a4.x, a4.y, a4.z, a4.w, b4.x, b4.y, b4.z, b4.w, in9};
                u64 p[9];
                #pragma unroll
                for (int k = 0; k < 9; k++) p[k] = pk(in[k], in[k + 1]);
                #pragma unroll
                for (int s = 0; s < 3; s++) {
                    const u64* wq = reinterpret_cast<const u64*>(&ws[(ic * 27 + (dz * 3 + dy) * 3 + s) * 9]);
                    #pragma unroll
                    for (int o = 0; o < 9; o++) {
                        u64 w = wq[o];
                        fma2(acc[o][0], p[s + 0], w);
                        fma2(acc[o][1], p[s + 2], w);
                        fma2(acc[o][2], p[s + 4], w);
                        fma2(acc[o][3], p[s + 6], w);
                    }
                }
            }
        }
    }
    size_t ob = (size_t)z * Pl + y * 128 + x0;
    #pragma unroll
    for (int o = 0; o < 9; o++) {
        float2 v0 = upk(acc[o][0]), v1 = upk(acc[o][1]);
        float2 v2 = upk(acc[o][2]), v3 = upk(acc[o][3]);
        float4 f0 = make_float4(v0.x, v0.y, v1.x, v1.y);
        float4 f1 = make_float4(v2.x, v2.y, v3.x, v3.y);
        size_t base = (size_t)(grp * 9 + o) * V + ob;
        *reinterpret_cast<float4*>(&g_w[base])     = f0;
        *reinterpret_cast<float4*>(&g_w[base + 4]) = f1;
    }
}

// ---------------------------------------------------------------------------
// adaptive conv, width 4, all 8 channels, fused L1 normalization.
// Inputs always padded (no bounds checks). src: 0=g_xp,1=g_tp,2=g_hp
// dst: 0=d_out(flat), 1=g_tp, 2=g_hp
// ---------------------------------------------------------------------------
__global__ __launch_bounds__(256) void k_adapt(float* __restrict__ dout,
                                               int src, int dst)
{
    const float* in  = (src == 0) ? g_xp : (src == 1 ? g_tp : g_hp);

    int x0 = threadIdx.x * 4;               // 32 threads cover the x row
    int y  = blockIdx.x * 8 + threadIdx.y;  // 8 y per block
    int z  = blockIdx.y;
    size_t ob  = (size_t)z * Pl + y * 128 + x0;                    // flat (weights, d_out)
    size_t ibp = (size_t)z * PPl + y * PX + x0 + 3;                // padded input base

    u64 acc[8][2];
    #pragma unroll
    for (int c = 0; c < 8; c++) { acc[c][0] = 0; acc[c][1] = 0; }
    u64 nrm[2] = {0, 0};

    #pragma unroll
    for (int dz = 0; dz < 3; dz++) {
        #pragma unroll
        for (int dy = 0; dy < 3; dy++) {
            // per-voxel weights at the OUTPUT position (all taps -> L1 norm)
            u64 q[3][2];
            #pragma unroll
            for (int s = 0; s < 3; s++) {
                const float* wr = g_w + (size_t)(dz * 9 + dy * 3 + s) * V + ob;
                float4 w0 = *reinterpret_cast<const float4*>(wr);
                q[s][0] = pk(w0.x, w0.y); q[s][1] = pk(w0.z, w0.w);
                nrm[0] = add2(nrm[0], abs2(q[s][0]));
                nrm[1] = add2(nrm[1], abs2(q[s][1]));
            }
            #pragma unroll
            for (int c = 0; c < 8; c++) {
                const float* r = in + (size_t)c * PV + ibp + dz * PPl + dy * PX;
                float in0 = r[0];
                float4 a4 = *reinterpret_cast<const float4*>(r + 1);
                float in5 = r[5];
                float iv[6] = {in0, a4.x, a4.y, a4.z, a4.w, in5};
                u64 p[5];
                #pragma unroll
                for (int k = 0; k < 5; k++) p[k] = pk(iv[k], iv[k + 1]);
                #pragma unroll
                for (int s = 0; s < 3; s++) {
                    fma2(acc[c][0], p[s + 0], q[s][0]);
                    fma2(acc[c][1], p[s + 2], q[s][1]);
                }
            }
        }
    }

    u64 rn[2];
    #pragma unroll
    for (int j = 0; j < 2; j++) {
        float2 n2 = upk(nrm[j]);
        rn[j] = pk(1.f / fmaxf(n2.x, 1e-12f), 1.f / fmaxf(n2.y, 1e-12f));
    }

    if (dst == 0) {
        #pragma unroll
        for (int c = 0; c < 8; c++) {
            float2 v0 = upk(mul2(acc[c][0], rn[0]));
            float2 v1 = upk(mul2(acc[c][1], rn[1]));
            *reinterpret_cast<float4*>(&dout[(size_t)c * V + ob]) =
                make_float4(v0.x, v0.y, v1.x, v1.y);
        }
    } else {
        float* out = (dst == 1) ? g_tp : g_hp;
        size_t op = (size_t)(z + 1) * PPl + (y + 1) * PX + (x0 + 4);
        #pragma unroll
        for (int c = 0; c < 8; c++) {
            float2 v0 = upk(mul2(acc[c][0], rn[0]));
            float2 v1 = upk(mul2(acc[c][1], rn[1]));
            *reinterpret_cast<float4*>(&out[(size_t)c * PV + op]) =
                make_float4(v0.x, v0.y, v1.x, v1.y);
        }
    }
}

// ---------------------------------------------------------------------------
extern "C" void kernel_launch(void* const* d_in, const int* in_sizes, int n_in,
                              void* d_out, int out_size)
{
    const float* x  = (const float*)d_in[0];
    const float* w1 = (n_in > 1) ? (const float*)d_in[1] : nullptr;
    const float* b1 = (n_in > 2) ? (const float*)d_in[2] : nullptr;
    const float* w2 = (n_in > 3) ? (const float*)d_in[3] : nullptr;
    for (int i = 0; i < n_in; i++) {
        switch (in_sizes[i]) {
            case 8 * V: x  = (const float*)d_in[i]; break;
            case 1728:  w1 = (const float*)d_in[i]; break;
            case 8:     b1 = (const float*)d_in[i]; break;
            case 5832:  w2 = (const float*)d_in[i]; break;
            default: break;
        }
    }

    k_pad<<<8 * 130 * 130, 160>>>(x);

    dim3 blk(16, 8);
    dim3 g1(16, 128);
    k_conv1<<<g1, blk>>>(w1, b1);
    k_conv2<<<dim3(16, 128, 3), blk>>>(w2);

    float* out = (float*)d_out;
    dim3 ablk(32, 8);
    k_adapt<<<g1, ablk>>>(out, 0, 1);   // g_xp -> g_tp
    k_adapt<<<g1, ablk>>>(out, 1, 2);   // g_tp -> g_hp
    k_adapt<<<g1, ablk>>>(out, 2, 0);   // g_hp -> d_out
}